// round 1
// baseline (speedup 1.0000x reference)
#include <cuda_runtime.h>

#define DQ 256      // dim
#define KQ 8192     // n_embed
#define NQ 32768    // queries
#define BM 128      // queries per block
#define BN 64       // codes per tile
#define BK 16       // dims per e-tile stage
#define XPAD 132    // padded row length for x smem (conflict + float4 align)

__device__ float g_embedT[KQ * DQ];   // [K][D], transposed codebook
__device__ float g_esq[KQ];           // ||e_k||^2

// ---------------- transpose embed[256][8192] -> embedT[8192][256] ----------------
__global__ void vq_transpose(const float* __restrict__ embed) {
    __shared__ float t[32][33];
    int k0 = blockIdx.x * 32;
    int d0 = blockIdx.y * 32;
    int tx = threadIdx.x, ty = threadIdx.y;
    #pragma unroll
    for (int j = ty; j < 32; j += 8)
        t[j][tx] = embed[(size_t)(d0 + j) * KQ + k0 + tx];
    __syncthreads();
    #pragma unroll
    for (int j = ty; j < 32; j += 8)
        g_embedT[(size_t)(k0 + j) * DQ + d0 + tx] = t[tx][j];
}

// ---------------- e_sq[k] = sum_d embedT[k][d]^2, one warp per code ----------------
__global__ void vq_esq() {
    int w    = threadIdx.x >> 5;
    int lane = threadIdx.x & 31;
    int k    = blockIdx.x * 8 + w;
    float s = 0.f;
    #pragma unroll
    for (int j = 0; j < 8; j++) {
        float v = g_embedT[(size_t)k * DQ + j * 32 + lane];
        s = fmaf(v, v, s);
    }
    #pragma unroll
    for (int o = 16; o; o >>= 1) s += __shfl_xor_sync(0xffffffffu, s, o);
    if (lane == 0) g_esq[k] = s;
}

// ---------------- fused dist-GEMM + argmin + gather ----------------
__global__ __launch_bounds__(256, 1)
void vq_main(const float* __restrict__ x, const float* __restrict__ embed,
             float* __restrict__ out) {
    extern __shared__ float smem[];
    float* xs   = smem;                    // [DQ][XPAD] x tile, dim-major
    float* es   = xs + DQ * XPAD;          // [2][BK*BN] e tiles (double buffer)
    float* redv = es + 2 * BK * BN;        // [BM][16]
    int*   redi = (int*)(redv + BM * 16);  // [BM][16]

    int tid = threadIdx.x;
    int tx  = tid & 15;      // 16 col-groups of 4 codes
    int ty  = tid >> 4;      // 16 row-groups
    int qbase = blockIdx.x * BM;

    // Load x tile transposed: xs[d][i] = x[qbase+i][d]   (tid == d, 256 threads)
    for (int i = 0; i < BM; i++)
        xs[tid * XPAD + i] = x[(size_t)(qbase + i) * DQ + tid];
    __syncthreads();

    float bestv[8];
    int   besti[8];
    #pragma unroll
    for (int r = 0; r < 8; r++) { bestv[r] = 3.4e38f; besti[r] = 0; }

    const int lr = tid >> 4;        // e-tile row (dim) for loads
    const int lc = (tid & 15) * 4;  // e-tile col (code) for loads

    for (int nt = 0; nt < KQ / BN; nt++) {
        float c[8][4];
        #pragma unroll
        for (int r = 0; r < 8; r++)
            #pragma unroll
            for (int cc = 0; cc < 4; cc++) c[r][cc] = 0.f;

        // prologue: stage 0
        {
            float4 v = *(const float4*)&embed[(size_t)lr * KQ + nt * BN + lc];
            *(float4*)&es[lr * BN + lc] = v;
        }
        __syncthreads();

        int buf = 0;
        for (int kt = 0; kt < DQ / BK; kt++) {
            float4 pre;
            const bool have_next = (kt < DQ / BK - 1);
            if (have_next)
                pre = *(const float4*)&embed[(size_t)((kt + 1) * BK + lr) * KQ + nt * BN + lc];

            const float* eb = es + buf * (BK * BN);
            #pragma unroll
            for (int kk = 0; kk < BK; kk++) {
                int d = kt * BK + kk;
                float4 a0 = *(const float4*)&xs[d * XPAD + ty * 4];
                float4 a1 = *(const float4*)&xs[d * XPAD + 64 + ty * 4];
                float4 b  = *(const float4*)&eb[kk * BN + tx * 4];
                c[0][0] = fmaf(a0.x, b.x, c[0][0]); c[0][1] = fmaf(a0.x, b.y, c[0][1]);
                c[0][2] = fmaf(a0.x, b.z, c[0][2]); c[0][3] = fmaf(a0.x, b.w, c[0][3]);
                c[1][0] = fmaf(a0.y, b.x, c[1][0]); c[1][1] = fmaf(a0.y, b.y, c[1][1]);
                c[1][2] = fmaf(a0.y, b.z, c[1][2]); c[1][3] = fmaf(a0.y, b.w, c[1][3]);
                c[2][0] = fmaf(a0.z, b.x, c[2][0]); c[2][1] = fmaf(a0.z, b.y, c[2][1]);
                c[2][2] = fmaf(a0.z, b.z, c[2][2]); c[2][3] = fmaf(a0.z, b.w, c[2][3]);
                c[3][0] = fmaf(a0.w, b.x, c[3][0]); c[3][1] = fmaf(a0.w, b.y, c[3][1]);
                c[3][2] = fmaf(a0.w, b.z, c[3][2]); c[3][3] = fmaf(a0.w, b.w, c[3][3]);
                c[4][0] = fmaf(a1.x, b.x, c[4][0]); c[4][1] = fmaf(a1.x, b.y, c[4][1]);
                c[4][2] = fmaf(a1.x, b.z, c[4][2]); c[4][3] = fmaf(a1.x, b.w, c[4][3]);
                c[5][0] = fmaf(a1.y, b.x, c[5][0]); c[5][1] = fmaf(a1.y, b.y, c[5][1]);
                c[5][2] = fmaf(a1.y, b.z, c[5][2]); c[5][3] = fmaf(a1.y, b.w, c[5][3]);
                c[6][0] = fmaf(a1.z, b.x, c[6][0]); c[6][1] = fmaf(a1.z, b.y, c[6][1]);
                c[6][2] = fmaf(a1.z, b.z, c[6][2]); c[6][3] = fmaf(a1.z, b.w, c[6][3]);
                c[7][0] = fmaf(a1.w, b.x, c[7][0]); c[7][1] = fmaf(a1.w, b.y, c[7][1]);
                c[7][2] = fmaf(a1.w, b.z, c[7][2]); c[7][3] = fmaf(a1.w, b.w, c[7][3]);
            }

            if (have_next)
                *(float4*)&es[(1 - buf) * (BK * BN) + lr * BN + lc] = pre;
            __syncthreads();
            buf ^= 1;
        }

        // epilogue for this code tile: dist = e_sq - 2*dot, running argmin
        float4 eq = *(const float4*)&g_esq[nt * BN + tx * 4];
        float eqa[4] = {eq.x, eq.y, eq.z, eq.w};
        #pragma unroll
        for (int cc = 0; cc < 4; cc++) {
            int col = nt * BN + tx * 4 + cc;
            #pragma unroll
            for (int r = 0; r < 8; r++) {
                float dist = fmaf(-2.f, c[r][cc], eqa[cc]);
                if (dist < bestv[r] || (dist == bestv[r] && col < besti[r])) {
                    bestv[r] = dist; besti[r] = col;
                }
            }
        }
    }

    // cross-thread reduction: rows ty*4+{0..3} and 64+ty*4+{0..3}
    #pragma unroll
    for (int g = 0; g < 2; g++) {
        #pragma unroll
        for (int j = 0; j < 4; j++) {
            int row = g * 64 + ty * 4 + j;
            redv[row * 16 + tx] = bestv[g * 4 + j];
            redi[row * 16 + tx] = besti[g * 4 + j];
        }
    }
    __syncthreads();

    if (tid < BM) {
        float bv = redv[tid * 16];
        int   bi = redi[tid * 16];
        #pragma unroll
        for (int t = 1; t < 16; t++) {
            float v  = redv[tid * 16 + t];
            int   ii = redi[tid * 16 + t];
            if (v < bv || (v == bv && ii < bi)) { bv = v; bi = ii; }
        }
        redi[tid * 16] = bi;   // final winner per row
    }
    __syncthreads();

    // gather: out[qbase+i][d] = embedT[best_i][d]  (tid == d)
    for (int i = 0; i < BM; i++) {
        int k = redi[i * 16];
        out[(size_t)(qbase + i) * DQ + tid] = g_embedT[(size_t)k * DQ + tid];
    }
}

extern "C" void kernel_launch(void* const* d_in, const int* in_sizes, int n_in,
                              void* d_out, int out_size) {
    const float* x     = (const float*)d_in[0];
    const float* embed = (const float*)d_in[1];
    float*       out   = (float*)d_out;

    vq_transpose<<<dim3(KQ / 32, DQ / 32), dim3(32, 8)>>>(embed);
    vq_esq<<<KQ / 8, 256>>>();

    size_t smembytes = (size_t)(DQ * XPAD + 2 * BK * BN + BM * 16) * 4 + (size_t)BM * 16 * 4;
    cudaFuncSetAttribute(vq_main, cudaFuncAttributeMaxDynamicSharedMemorySize, (int)smembytes);
    vq_main<<<NQ / BM, 256, smembytes>>>(x, embed, out);
}

// round 2
// speedup vs baseline: 1.1187x; 1.1187x over previous
#include <cuda_runtime.h>

#define DQ 256      // dim
#define KQ 8192     // n_embed
#define NQ 32768    // queries
#define BM 128      // queries per block
#define BN 64       // codes per tile
#define BK 16       // dims per e-tile stage
#define XPAD 132    // padded row length for x smem (conflict + float4 align)

typedef unsigned long long u64;

__device__ __forceinline__ u64 pack2_dup(float v) {
    u64 r;
    asm("mov.b64 %0, {%1, %1};" : "=l"(r) : "f"(v));
    return r;
}
__device__ __forceinline__ void unpack2(u64 v, float& lo, float& hi) {
    asm("mov.b64 {%0, %1}, %2;" : "=f"(lo), "=f"(hi) : "l"(v));
}
__device__ __forceinline__ u64 fma2(u64 a, u64 b, u64 c) {
    u64 d;
    asm("fma.rn.f32x2 %0, %1, %2, %3;" : "=l"(d) : "l"(a), "l"(b), "l"(c));
    return d;
}

__device__ float g_embedT[KQ * DQ];   // [K][D], transposed codebook
__device__ float g_esq[KQ];           // ||e_k||^2

// ---------------- transpose embed[256][8192] -> embedT[8192][256] ----------------
__global__ void vq_transpose(const float* __restrict__ embed) {
    __shared__ float t[32][33];
    int k0 = blockIdx.x * 32;
    int d0 = blockIdx.y * 32;
    int tx = threadIdx.x, ty = threadIdx.y;
    #pragma unroll
    for (int j = ty; j < 32; j += 8)
        t[j][tx] = embed[(size_t)(d0 + j) * KQ + k0 + tx];
    __syncthreads();
    #pragma unroll
    for (int j = ty; j < 32; j += 8)
        g_embedT[(size_t)(k0 + j) * DQ + d0 + tx] = t[tx][j];
}

// ---------------- e_sq[k] = sum_d embedT[k][d]^2, one warp per code ----------------
__global__ void vq_esq() {
    int w    = threadIdx.x >> 5;
    int lane = threadIdx.x & 31;
    int k    = blockIdx.x * 8 + w;
    float s = 0.f;
    #pragma unroll
    for (int j = 0; j < 8; j++) {
        float v = g_embedT[(size_t)k * DQ + j * 32 + lane];
        s = fmaf(v, v, s);
    }
    #pragma unroll
    for (int o = 16; o; o >>= 1) s += __shfl_xor_sync(0xffffffffu, s, o);
    if (lane == 0) g_esq[k] = s;
}

// ---------------- fused dist-GEMM (FFMA2) + argmin + gather ----------------
__global__ __launch_bounds__(256, 1)
void vq_main(const float* __restrict__ x, const float* __restrict__ embed,
             float* __restrict__ out) {
    extern __shared__ float smem[];
    float* xs   = smem;                    // [DQ][XPAD] x tile, dim-major
    float* es   = xs + DQ * XPAD;          // [2][BK*BN] e tiles (double buffer)
    float* redv = es + 2 * BK * BN;        // [BM][16]
    int*   redi = (int*)(redv + BM * 16);  // [BM][16]

    int tid = threadIdx.x;
    int tx  = tid & 15;      // 16 col-groups of 4 codes
    int ty  = tid >> 4;      // 16 row-groups
    int qbase = blockIdx.x * BM;

    // Load x tile transposed: xs[d][i] = x[qbase+i][d]   (tid == d, 256 threads)
    for (int i = 0; i < BM; i++)
        xs[tid * XPAD + i] = x[(size_t)(qbase + i) * DQ + tid];
    __syncthreads();

    float bestv[8];
    int   besti[8];
    #pragma unroll
    for (int r = 0; r < 8; r++) { bestv[r] = 3.4e38f; besti[r] = 0; }

    const int lr = tid >> 4;        // e-tile row (dim) for loads
    const int lc = (tid & 15) * 4;  // e-tile col (code) for loads

    for (int nt = 0; nt < KQ / BN; nt++) {
        // 16 packed accumulators: 4 row-pairs x 4 cols
        u64 c2[4][4];
        #pragma unroll
        for (int rp = 0; rp < 4; rp++)
            #pragma unroll
            for (int cc = 0; cc < 4; cc++) c2[rp][cc] = 0ull;

        // prologue: stage 0
        {
            float4 v = *(const float4*)&embed[(size_t)lr * KQ + nt * BN + lc];
            *(float4*)&es[lr * BN + lc] = v;
        }
        __syncthreads();

        int buf = 0;
        for (int kt = 0; kt < DQ / BK; kt++) {
            float4 pre;
            const bool have_next = (kt < DQ / BK - 1);
            if (have_next)
                pre = *(const float4*)&embed[(size_t)((kt + 1) * BK + lr) * KQ + nt * BN + lc];

            const float* eb = es + buf * (BK * BN);
            #pragma unroll
            for (int kk = 0; kk < BK; kk++) {
                int d = kt * BK + kk;
                // a-pairs: adjacent rows packed for free by 128-bit loads
                ulonglong2 a0 = *(const ulonglong2*)&xs[d * XPAD + ty * 4];
                ulonglong2 a1 = *(const ulonglong2*)&xs[d * XPAD + 64 + ty * 4];
                float4 b = *(const float4*)&eb[kk * BN + tx * 4];
                u64 bp0 = pack2_dup(b.x);
                u64 bp1 = pack2_dup(b.y);
                u64 bp2 = pack2_dup(b.z);
                u64 bp3 = pack2_dup(b.w);
                c2[0][0] = fma2(a0.x, bp0, c2[0][0]);
                c2[0][1] = fma2(a0.x, bp1, c2[0][1]);
                c2[0][2] = fma2(a0.x, bp2, c2[0][2]);
                c2[0][3] = fma2(a0.x, bp3, c2[0][3]);
                c2[1][0] = fma2(a0.y, bp0, c2[1][0]);
                c2[1][1] = fma2(a0.y, bp1, c2[1][1]);
                c2[1][2] = fma2(a0.y, bp2, c2[1][2]);
                c2[1][3] = fma2(a0.y, bp3, c2[1][3]);
                c2[2][0] = fma2(a1.x, bp0, c2[2][0]);
                c2[2][1] = fma2(a1.x, bp1, c2[2][1]);
                c2[2][2] = fma2(a1.x, bp2, c2[2][2]);
                c2[2][3] = fma2(a1.x, bp3, c2[2][3]);
                c2[3][0] = fma2(a1.y, bp0, c2[3][0]);
                c2[3][1] = fma2(a1.y, bp1, c2[3][1]);
                c2[3][2] = fma2(a1.y, bp2, c2[3][2]);
                c2[3][3] = fma2(a1.y, bp3, c2[3][3]);
            }

            if (have_next)
                *(float4*)&es[(1 - buf) * (BK * BN) + lr * BN + lc] = pre;
            __syncthreads();
            buf ^= 1;
        }

        // epilogue: dist = e_sq - 2*dot, running argmin
        // row mapping: rp0 -> rows ty*4+0/1, rp1 -> ty*4+2/3, rp2 -> 64+ty*4+0/1, rp3 -> 64+ty*4+2/3
        float4 eq = *(const float4*)&g_esq[nt * BN + tx * 4];
        float eqa[4] = {eq.x, eq.y, eq.z, eq.w};
        #pragma unroll
        for (int cc = 0; cc < 4; cc++) {
            int col = nt * BN + tx * 4 + cc;
            #pragma unroll
            for (int rp = 0; rp < 4; rp++) {
                float lo, hi;
                unpack2(c2[rp][cc], lo, hi);
                int r0 = (rp >> 1) * 4 + (rp & 1) * 2;   // 0,2,4,6
                float dlo = fmaf(-2.f, lo, eqa[cc]);
                float dhi = fmaf(-2.f, hi, eqa[cc]);
                if (dlo < bestv[r0] || (dlo == bestv[r0] && col < besti[r0])) {
                    bestv[r0] = dlo; besti[r0] = col;
                }
                if (dhi < bestv[r0 + 1] || (dhi == bestv[r0 + 1] && col < besti[r0 + 1])) {
                    bestv[r0 + 1] = dhi; besti[r0 + 1] = col;
                }
            }
        }
    }

    // cross-thread reduction
    // bestv index mapping: 0..3 -> rows ty*4+{0,2} pairs... reconstruct explicit rows:
    // bestv[0]=row ty*4+0, [1]=ty*4+1, [2]=ty*4+2, [3]=ty*4+3 ?  NO:
    // r0 sequence above: rp0->(0,1), rp1->(2,3), rp2->(4,5), rp3->(6,7)
    // so bestv[0..3] = rows ty*4+0..3, bestv[4..7] = rows 64+ty*4+0..3. Same as before.
    #pragma unroll
    for (int g = 0; g < 2; g++) {
        #pragma unroll
        for (int j = 0; j < 4; j++) {
            int row = g * 64 + ty * 4 + j;
            redv[row * 16 + tx] = bestv[g * 4 + j];
            redi[row * 16 + tx] = besti[g * 4 + j];
        }
    }
    __syncthreads();

    if (tid < BM) {
        float bv = redv[tid * 16];
        int   bi = redi[tid * 16];
        #pragma unroll
        for (int t = 1; t < 16; t++) {
            float v  = redv[tid * 16 + t];
            int   ii = redi[tid * 16 + t];
            if (v < bv || (v == bv && ii < bi)) { bv = v; bi = ii; }
        }
        redi[tid * 16] = bi;   // final winner per row
    }
    __syncthreads();

    // gather: out[qbase+i][d] = embedT[best_i][d]  (tid == d)
    for (int i = 0; i < BM; i++) {
        int k = redi[i * 16];
        out[(size_t)(qbase + i) * DQ + tid] = g_embedT[(size_t)k * DQ + tid];
    }
}

extern "C" void kernel_launch(void* const* d_in, const int* in_sizes, int n_in,
                              void* d_out, int out_size) {
    const float* x     = (const float*)d_in[0];
    const float* embed = (const float*)d_in[1];
    float*       out   = (float*)d_out;

    vq_transpose<<<dim3(KQ / 32, DQ / 32), dim3(32, 8)>>>(embed);
    vq_esq<<<KQ / 8, 256>>>();

    size_t smembytes = (size_t)(DQ * XPAD + 2 * BK * BN + BM * 16) * 4 + (size_t)BM * 16 * 4;
    cudaFuncSetAttribute(vq_main, cudaFuncAttributeMaxDynamicSharedMemorySize, (int)smembytes);
    vq_main<<<NQ / BM, 256, smembytes>>>(x, embed, out);
}

// round 6
// speedup vs baseline: 4.2161x; 3.7688x over previous
#include <cuda_runtime.h>
#include <cuda_bf16.h>
#include <cuda_fp16.h>
#include <cstdint>

#define DQ 256
#define KQ 8192
#define NQ 32768

typedef unsigned int u32;

// ---------------- device scratch ----------------
__device__ float          g_embedT[KQ * DQ];        // fp32 [K][D]
__device__ __nv_bfloat16  g_ebB[KQ * DQ];           // bf16 [K][D]
__device__ __nv_bfloat16  g_xb[NQ * DQ];            // bf16 [N][D]
__device__ float          g_esq[KQ];
__device__ __half         g_S[(size_t)NQ * KQ];     // fp16 (dist-256), 512MB

// ---------------- helpers ----------------
__device__ __forceinline__ u32 smem_u32(const void* p) {
    u32 a;
    asm("{ .reg .u64 t; cvta.to.shared.u64 t, %1; cvt.u32.u64 %0, t; }" : "=r"(a) : "l"(p));
    return a;
}
__device__ __forceinline__ void cp16(u32 saddr, const void* g) {
    asm volatile("cp.async.cg.shared.global [%0], [%1], 16;" :: "r"(saddr), "l"(g));
}
__device__ __forceinline__ void cp_commit() { asm volatile("cp.async.commit_group;"); }
__device__ __forceinline__ void cp_wait1()  { asm volatile("cp.async.wait_group 1;" ::: "memory"); }
__device__ __forceinline__ void cp_wait0()  { asm volatile("cp.async.wait_group 0;" ::: "memory"); }

#define LDSM_X4(r, addr) \
    asm volatile("ldmatrix.sync.aligned.m8n8.x4.shared.b16 {%0,%1,%2,%3}, [%4];" \
                 : "=r"((r)[0]), "=r"((r)[1]), "=r"((r)[2]), "=r"((r)[3]) : "r"(addr))

#define MMA16816(c, a, b0, b1) \
    asm volatile("mma.sync.aligned.m16n8k16.row.col.f32.bf16.bf16.f32 " \
                 "{%0,%1,%2,%3}, {%4,%5,%6,%7}, {%8,%9}, {%0,%1,%2,%3};" \
                 : "+f"((c)[0]), "+f"((c)[1]), "+f"((c)[2]), "+f"((c)[3]) \
                 : "r"((a)[0]), "r"((a)[1]), "r"((a)[2]), "r"((a)[3]), "r"(b0), "r"(b1))

// ---------------- prep kernels ----------------
__global__ void vq_transpose(const float* __restrict__ embed) {
    __shared__ float t[32][33];
    int k0 = blockIdx.x * 32, d0 = blockIdx.y * 32;
    int tx = threadIdx.x, ty = threadIdx.y;
    #pragma unroll
    for (int j = ty; j < 32; j += 8)
        t[j][tx] = embed[(size_t)(d0 + j) * KQ + k0 + tx];
    __syncthreads();
    #pragma unroll
    for (int j = ty; j < 32; j += 8) {
        float v = t[tx][j];
        g_embedT[(size_t)(k0 + j) * DQ + d0 + tx] = v;
        g_ebB[(size_t)(k0 + j) * DQ + d0 + tx]    = __float2bfloat16(v);
    }
}

__global__ void vq_esq() {
    int w = threadIdx.x >> 5, lane = threadIdx.x & 31;
    int k = blockIdx.x * 8 + w;
    float s = 0.f;
    #pragma unroll
    for (int j = 0; j < 8; j++) {
        float v = g_embedT[(size_t)k * DQ + j * 32 + lane];
        s = fmaf(v, v, s);
    }
    #pragma unroll
    for (int o = 16; o; o >>= 1) s += __shfl_xor_sync(0xffffffffu, s, o);
    if (lane == 0) g_esq[k] = s;
}

__global__ void vq_x2bf(const float* __restrict__ x) {
    int i = blockIdx.x * blockDim.x + threadIdx.x;  // one float4
    float4 v = *(const float4*)&x[(size_t)i * 4];
    __nv_bfloat16* o = &g_xb[(size_t)i * 4];
    o[0] = __float2bfloat16(v.x); o[1] = __float2bfloat16(v.y);
    o[2] = __float2bfloat16(v.z); o[3] = __float2bfloat16(v.w);
}

// ---------------- GEMM: bf16 mma.sync, dist-256 -> fp16 S ----------------
// CTA: 128 queries x full K loop (128 tiles of 64 codes). 8 warps as 4M x 2N,
// warp tile 32x32. A smem 128x256 bf16 (pitch 528B), B double-buffered 64x256.
#define GM_BM    128
#define GM_BN    64
#define APITCH   528          // bytes per row (264 bf16) -> conflict-free ldmatrix
#define A_OFF    0            // 128*528 = 67584
#define B_OFF    67584        // 2 x 64*528 = 67584
#define B_BUF    33792
#define ST_OFF   135168       // stage: 128 x 72 halfs (144B pitch) = 18432
#define ST_PITCH 144
#define GM_SMEM  153600

__global__ __launch_bounds__(256, 1)
void vq_gemm() {
    extern __shared__ char smem[];
    u32 sb  = smem_u32(smem);
    int tid  = threadIdx.x;
    int wid  = tid >> 5, lane = tid & 31;
    int wm   = wid >> 1;          // 0..3  (M group of 32 rows)
    int wn   = wid & 1;           // 0..1  (N group of 32 cols)
    int qbase = blockIdx.x * GM_BM;

    // prologue: A tile = 128 rows x 32 chunks (4096), B buf0 = 64 x 32 (2048)
    #pragma unroll
    for (int i = 0; i < 16; i++) {
        int id = tid + i * 256;
        int r = id >> 5, c = id & 31;
        cp16(sb + A_OFF + (u32)r * APITCH + (u32)c * 16,
             &g_xb[(size_t)(qbase + r) * DQ + c * 8]);
    }
    #pragma unroll
    for (int i = 0; i < 8; i++) {
        int id = tid + i * 256;
        int r = id >> 5, c = id & 31;
        cp16(sb + B_OFF + (u32)r * APITCH + (u32)c * 16,
             &g_ebB[(size_t)r * DQ + c * 8]);
    }
    cp_commit();

    // per-thread ldmatrix base offsets
    u32 lrow = (u32)(lane & 15);
    u32 lcol = (u32)(lane >> 4) * 16;     // bytes (+8 halfs)
    u32 a_base = sb + A_OFF + ((u32)wm * 32 + lrow) * APITCH + lcol;
    u32 b_rowoff = ((u32)wn * 32 + lrow) * APITCH + lcol;

    int ep_r0  = wm * 32 + (lane >> 2);           // epilogue row (frag row 0)
    int ep_c0  = wn * 32 + (lane & 3) * 2;        // epilogue col base

    for (int nt = 0; nt < KQ / GM_BN; nt++) {
        // prefetch next B
        if (nt + 1 < KQ / GM_BN) {
            int nb = (nt + 1) * GM_BN;
            u32 bb = sb + B_OFF + (u32)((nt + 1) & 1) * B_BUF;
            #pragma unroll
            for (int i = 0; i < 8; i++) {
                int id = tid + i * 256;
                int r = id >> 5, c = id & 31;
                cp16(bb + (u32)r * APITCH + (u32)c * 16,
                     &g_ebB[(size_t)(nb + r) * DQ + c * 8]);
            }
            cp_commit();
            cp_wait1();
        } else {
            cp_wait0();
        }
        __syncthreads();

        u32 bbase = sb + B_OFF + (u32)(nt & 1) * B_BUF + b_rowoff;

        float c[2][4][4];
        #pragma unroll
        for (int mf = 0; mf < 2; mf++)
            #pragma unroll
            for (int nf = 0; nf < 4; nf++)
                #pragma unroll
                for (int j = 0; j < 4; j++) c[mf][nf][j] = 0.f;

        #pragma unroll
        for (int k = 0; k < DQ / 16; k++) {
            u32 koff = (u32)k * 32;   // 16 halfs = 32 bytes
            u32 a0[4], a1[4], b0[4], b1[4];
            LDSM_X4(a0, a_base + koff);
            LDSM_X4(a1, a_base + 16 * APITCH + koff);
            LDSM_X4(b0, bbase + koff);
            LDSM_X4(b1, bbase + 16 * APITCH + koff);
            MMA16816(c[0][0], a0, b0[0], b0[2]);
            MMA16816(c[0][1], a0, b0[1], b0[3]);
            MMA16816(c[0][2], a0, b1[0], b1[2]);
            MMA16816(c[0][3], a0, b1[1], b1[3]);
            MMA16816(c[1][0], a1, b0[0], b0[2]);
            MMA16816(c[1][1], a1, b0[1], b0[3]);
            MMA16816(c[1][2], a1, b1[0], b1[2]);
            MMA16816(c[1][3], a1, b1[1], b1[3]);
        }

        // epilogue: dist-256 -> fp16 -> stage smem
        #pragma unroll
        for (int mf = 0; mf < 2; mf++) {
            int r0 = ep_r0 + mf * 16;
            #pragma unroll
            for (int nf = 0; nf < 4; nf++) {
                int col = ep_c0 + (nf >> 1) * 16 + (nf & 1) * 8;   // 0..63
                float2 eq = __ldg((const float2*)&g_esq[nt * GM_BN + col]);
                float d0 = fmaf(-2.f, c[mf][nf][0], eq.x) - 256.f;
                float d1 = fmaf(-2.f, c[mf][nf][1], eq.y) - 256.f;
                float d2 = fmaf(-2.f, c[mf][nf][2], eq.x) - 256.f;
                float d3 = fmaf(-2.f, c[mf][nf][3], eq.y) - 256.f;
                __half2 h01 = __floats2half2_rn(d0, d1);
                __half2 h23 = __floats2half2_rn(d2, d3);
                u32 sa0 = sb + ST_OFF + (u32)r0 * ST_PITCH + (u32)col * 2;
                u32 sa1 = sa0 + 8 * ST_PITCH;
                asm volatile("st.shared.b32 [%0], %1;" :: "r"(sa0), "r"(*(u32*)&h01) : "memory");
                asm volatile("st.shared.b32 [%0], %1;" :: "r"(sa1), "r"(*(u32*)&h23) : "memory");
            }
        }
        __syncthreads();

        // coalesced 16B stores to g_S
        #pragma unroll
        for (int i = 0; i < 4; i++) {
            int id = tid + i * 256;       // 1024 chunks
            int r = id >> 3, c16 = id & 7;
            u32 sa = sb + ST_OFF + (u32)r * ST_PITCH + (u32)c16 * 16;
            u32 v0, v1, v2, v3;
            asm volatile("ld.shared.v4.b32 {%0,%1,%2,%3}, [%4];"
                         : "=r"(v0), "=r"(v1), "=r"(v2), "=r"(v3) : "r"(sa));
            *(uint4*)&g_S[(size_t)(qbase + r) * KQ + nt * GM_BN + c16 * 8] =
                make_uint4(v0, v1, v2, v3);
        }
        __syncthreads();
    }
}

// ---------------- rescore: scan fp16 row, fp32 rescore candidates ----------------
#define MARGIN 2.5f
#define MAXC   64

__global__ __launch_bounds__(256, 4)
void vq_rescore(const float* __restrict__ x, float* __restrict__ out) {
    __shared__ float xrow[DQ];
    __shared__ float red[8];
    __shared__ int   cand[MAXC];
    __shared__ int   s_cnt;
    __shared__ int   s_bestk;
    __shared__ float s_bestv;

    int row = blockIdx.x;
    int tid = threadIdx.x;
    int wid = tid >> 5, lane = tid & 31;

    xrow[tid] = x[(size_t)row * DQ + tid];
    if (tid == 0) { s_cnt = 0; s_bestv = 3.4e38f; s_bestk = 0x7fffffff; }

    uint4 v[4];
    const uint4* Sp = (const uint4*)&g_S[(size_t)row * KQ];
    float mn = 3.4e38f;
    #pragma unroll
    for (int i = 0; i < 4; i++) {
        v[i] = Sp[tid + i * 256];
        const __half* h = (const __half*)&v[i];
        #pragma unroll
        for (int j = 0; j < 8; j++) mn = fminf(mn, __half2float(h[j]));
    }
    #pragma unroll
    for (int o = 16; o; o >>= 1) mn = fminf(mn, __shfl_xor_sync(0xffffffffu, mn, o));
    if (lane == 0) red[wid] = mn;
    __syncthreads();
    if (tid == 0) {
        float m = red[0];
        #pragma unroll
        for (int w = 1; w < 8; w++) m = fminf(m, red[w]);
        red[0] = m;
    }
    __syncthreads();
    float thr = red[0] + MARGIN;

    #pragma unroll
    for (int i = 0; i < 4; i++) {
        const __half* h = (const __half*)&v[i];
        #pragma unroll
        for (int j = 0; j < 8; j++) {
            if (__half2float(h[j]) <= thr) {
                int p = atomicAdd(&s_cnt, 1);
                if (p < MAXC) cand[p] = (tid + i * 256) * 8 + j;
            }
        }
    }
    __syncthreads();

    int cnt = s_cnt; if (cnt > MAXC) cnt = MAXC;

    for (int j = 0; j < cnt; j++) {
        int k = cand[j];
        float p = xrow[tid] * g_embedT[(size_t)k * DQ + tid];
        #pragma unroll
        for (int o = 16; o; o >>= 1) p += __shfl_xor_sync(0xffffffffu, p, o);
        if (lane == 0) red[wid] = p;
        __syncthreads();
        if (tid == 0) {
            float dot = red[0];
            #pragma unroll
            for (int w = 1; w < 8; w++) dot += red[w];
            float dist = fmaf(-2.f, dot, g_esq[k]);
            if (dist < s_bestv || (dist == s_bestv && k < s_bestk)) {
                s_bestv = dist; s_bestk = k;
            }
        }
        __syncthreads();
    }

    int bk = s_bestk;
    if (bk < 0 || bk >= KQ) bk = 0;   // safety net (should never trigger)
    out[(size_t)row * DQ + tid] = g_embedT[(size_t)bk * DQ + tid];
}

// ---------------- launch ----------------
extern "C" void kernel_launch(void* const* d_in, const int* in_sizes, int n_in,
                              void* d_out, int out_size) {
    const float* x     = (const float*)d_in[0];
    const float* embed = (const float*)d_in[1];
    float*       out   = (float*)d_out;

    vq_transpose<<<dim3(KQ / 32, DQ / 32), dim3(32, 8)>>>(embed);
    vq_esq<<<KQ / 8, 256>>>();
    vq_x2bf<<<(NQ * DQ / 4) / 256, 256>>>(x);

    cudaFuncSetAttribute(vq_gemm, cudaFuncAttributeMaxDynamicSharedMemorySize, GM_SMEM);
    vq_gemm<<<NQ / GM_BM, 256, GM_SMEM>>>();

    vq_rescore<<<NQ, 256>>>(x, out);
}